// round 17
// baseline (speedup 1.0000x reference)
#include <cuda_runtime.h>
#include <math.h>

// Fixed problem shapes
#define BS     4
#define C_     64
#define H_     64
#define W_     64
#define HW     4096     // H*W
#define NPTS   4096
#define M_TOT  (BS*HW)  // 16384

#define CELL   4
#define GRIDC  16       // 64/CELL
#define NCELL  (GRIDC*GRIDC)
#define CAP    64       // max points per cell (mean 16; +12 sigma unreachable)
#define CAND_CAP 640    // >= 9*CAP impossible; actual total ~144

#define LRELU_SLOPE 0.1f

// ---------------- device scratch (no allocations allowed) ----------------
__device__ float  g_f3t[BS * NPTS * C_];          // feat_3d transposed [b][n][c] (4 MB)
__device__ float4 g_cellpts[BS * NCELL * CAP];    // per-cell point arrays (1 MB)
__device__ int    g_ccount[BS * NCELL];           // zero at load; re-zeroed by K3 each call
__device__ int    g_knn[M_TOT * 3];               // knn indices

// ---------------- K1a: direct-scatter binning (64 blocks, 1 pt/thread) ----------------
__global__ void bin_points(const float* __restrict__ uv) {
    int b     = blockIdx.x >> 4;
    int slice = blockIdx.x & 15;
    int n     = slice * 256 + threadIdx.x;
    const float* uvb = uv + (size_t)b * 2 * NPTS;
    float u = uvb[n], v = uvb[NPTS + n];
    int cx = (int)(u * 0.25f);    // exact power-of-2 scale -> floor
    int cy = (int)(v * 0.25f);
    int c  = b * NCELL + cy * GRIDC + cx;
    int pos = atomicAdd(&g_ccount[c], 1);
    if (pos < CAP)
        g_cellpts[(size_t)c * CAP + pos] =
            make_float4(u, v,
                        __fadd_rn(__fmul_rn(u, u), __fmul_rn(v, v)),
                        __int_as_float(n));
}

// ---------------- K1b: transpose feat_3d (b,C,N) -> (b,N,C), float4 both ways ----------------
__global__ void transpose_f3(const float* __restrict__ f3) {
    __shared__ float tile[32][33];
    int tid = threadIdx.x;            // 128
    int b   = blockIdx.x >> 8;
    int rem = blockIdx.x & 255;
    int c0  = (rem >> 7) * 32;
    int n0  = (rem & 127) * 32;
    const float* src = f3 + ((size_t)(b * C_ + c0)) * NPTS + n0;
    #pragma unroll
    for (int k = 0; k < 2; k++) {
        int idx  = tid + k * 128;
        int row  = idx >> 3;          // c within tile
        int col4 = idx & 7;           // float4 slot along n
        float4 v = *(const float4*)(src + row * NPTS + col4 * 4);
        tile[row][col4 * 4 + 0] = v.x;
        tile[row][col4 * 4 + 1] = v.y;
        tile[row][col4 * 4 + 2] = v.z;
        tile[row][col4 * 4 + 3] = v.w;
    }
    __syncthreads();
    float* dst = g_f3t + ((size_t)(b * NPTS + n0)) * C_ + c0;
    #pragma unroll
    for (int k = 0; k < 2; k++) {
        int idx  = tid + k * 128;
        int n    = idx >> 3;          // n within tile
        int col4 = idx & 7;           // float4 slot along c
        float4 v = make_float4(tile[col4 * 4 + 0][n],
                               tile[col4 * 4 + 1][n],
                               tile[col4 * 4 + 2][n],
                               tile[col4 * 4 + 3][n]);
        *(float4*)(dst + n * C_ + col4 * 4) = v;
    }
}

// ---------------- K2: warp-cooperative KNN (validated) ----------------
// d rounding identical: cross = fma(fy, v, rn(fx*u)); d = rn(rn(g2+u2) - rn(2*cross))
// Selection: (d, idx) lexicographic -> order-independent, matches top_k ties.
#define INS(dv, iv)                                                     \
    if ((dv) < d2 || ((dv) == d2 && (iv) < i2)) {                       \
        if ((dv) < d1 || ((dv) == d1 && (iv) < i1)) {                   \
            d2 = d1; i2 = i1;                                           \
            if ((dv) < d0 || ((dv) == d0 && (iv) < i0)) {               \
                d1 = d0; i1 = i0; d0 = (dv); i0 = (iv);                 \
            } else { d1 = (dv); i1 = (iv); }                            \
        } else { d2 = (dv); i2 = (iv); }                                \
    }

__global__ void knn_search() {
    __shared__ float4 cand[CAND_CAP];

    int b    = blockIdx.x >> 8;
    int cell = blockIdx.x & 255;
    int cx = cell & (GRIDC - 1), cy = cell >> 4;
    int tid = threadIdx.x;            // 128

    int xlo = max(cx - 1, 0), xhi = min(cx + 1, GRIDC - 1);
    int ylo = max(cy - 1, 0), yhi = min(cy + 1, GRIDC - 1);
    int cbase[9], ccnt[9], coff[9], nc = 0, total = 0;
    for (int y = ylo; y <= yhi; y++)
        for (int x = xlo; x <= xhi; x++) {
            int c = b * NCELL + y * GRIDC + x;
            int n = __ldg(&g_ccount[c]);
            if (n > CAP) n = CAP;
            cbase[nc] = c * CAP; ccnt[nc] = n; coff[nc] = total;
            total += n; nc++;
        }

    for (int k = 0; k < nc; k++)
        for (int i = tid; i < ccnt[k]; i += 128)
            cand[coff[k] + i] = g_cellpts[(size_t)cbase[k] + i];
    __syncthreads();

    int g   = tid >> 3;               // 0..15
    int sub = tid & 7;
    int px = cx * CELL + (g & 3);
    int py = cy * CELL + (g >> 2);
    float fx = (float)px, fy = (float)py;
    float g2 = fx * fx + fy * fy;     // exact (small ints)

    float d0 = 3.4e38f, d1 = 3.4e38f, d2 = 3.4e38f;
    int   i0 = 0x7fffffff, i1 = 0x7fffffff, i2 = 0x7fffffff;

    for (int p = sub; p < total; p += 8) {
        float4 P = cand[p];
        float cross = __fmaf_rn(fy, P.y, __fmul_rn(fx, P.x));
        float d = __fsub_rn(__fadd_rn(g2, P.z), __fadd_rn(cross, cross));
        int idx = __float_as_int(P.w);
        INS(d, idx);
    }

    #pragma unroll
    for (int off = 4; off > 0; off >>= 1) {
        float e0 = __shfl_down_sync(0xffffffffu, d0, off, 8);
        int   j0 = __shfl_down_sync(0xffffffffu, i0, off, 8);
        float e1 = __shfl_down_sync(0xffffffffu, d1, off, 8);
        int   j1 = __shfl_down_sync(0xffffffffu, i1, off, 8);
        float e2 = __shfl_down_sync(0xffffffffu, d2, off, 8);
        int   j2 = __shfl_down_sync(0xffffffffu, i2, off, 8);
        INS(e0, j0);
        INS(e1, j1);
        INS(e2, j2);
    }

    if (sub == 0) {
        for (int rc = 2; rc < GRIDC; rc++) {
            float lb = (float)(CELL * (rc - 1));
            if (lb * lb > d2 + 0.5f) break;   // false while d2 = INF
            int Xlo = max(cx - rc, 0), Xhi = min(cx + rc, GRIDC - 1);
            int Ylo = max(cy - rc, 0), Yhi = min(cy + rc, GRIDC - 1);
            for (int y = Ylo; y <= Yhi; y++)
                for (int x = Xlo; x <= Xhi; x++) {
                    if (y != cy - rc && y != cy + rc && x != cx - rc && x != cx + rc)
                        continue;
                    int c = b * NCELL + y * GRIDC + x;
                    int n = __ldg(&g_ccount[c]);
                    if (n > CAP) n = CAP;
                    const float4* cp = g_cellpts + (size_t)c * CAP;
                    for (int p = 0; p < n; p++) {
                        float4 P = cp[p];
                        float cross = __fmaf_rn(fy, P.y, __fmul_rn(fx, P.x));
                        float d = __fsub_rn(__fadd_rn(g2, P.z), __fadd_rn(cross, cross));
                        int idx = __float_as_int(P.w);
                        INS(d, idx);
                    }
                }
        }
        int m = b * HW + py * 64 + px;
        g_knn[m * 3] = i0; g_knn[m * 3 + 1] = i1; g_knn[m * 3 + 2] = i2;
    }
}
#undef INS

// ---------------- K3: fused score + GEMM, warp-split score, 512 threads ----------------
// 256 blocks x 512 threads (16 warps); m-tile 64.
// Score: warp (qg = wid>>1, half = wid&1) computes channel-half of 8 queries.
//   ha/hb computed redundantly in both halves (bit-identical); z chain = 3 accumulators,
//   identical fma order/operands as validated 6-acc version -> same rounding.
// GEMM: thread = (row = lane + 32*(wid&1), og = wid>>1), 8 outputs, c-ascending fma.
__global__ void __launch_bounds__(512, 2)
fused_score_gemm(const float* __restrict__ uv,
                 const float* __restrict__ w1, const float* __restrict__ b1,
                 const float* __restrict__ w2, const float* __restrict__ b2,
                 const float* __restrict__ w_out,
                 const float* __restrict__ b_out,
                 float* __restrict__ out) {
    __shared__ float Wt[64 * 64];     // [c][o] for LDS.128 reads
    __shared__ float Fs[64 * 64];     // swizzled: row r, col (c+r)&63

    int tid  = threadIdx.x;
    int lane = tid & 31;
    int wid  = tid >> 5;              // 16 warps
    int m0   = blockIdx.x * 64;

    // reset cell counts for next call (counts already consumed by K2)
    if (blockIdx.x == 0 && tid < 256) {
        #pragma unroll
        for (int k = 0; k < (BS * NCELL) / 256; k++)
            g_ccount[tid + k * 256] = 0;
    }

    for (int idx = tid; idx < 4096; idx += 512) {
        int o = idx >> 6, c = idx & 63;
        Wt[c * 64 + o] = w_out[idx];
    }

    // ---- phase 1: score, warp-split by channel half ----
    int half = wid & 1;               // 0: channels 0-31, 1: channels 32-63
    int qg   = wid >> 1;              // 0..7 query group (8 queries each)
    int ch   = lane + 32 * half;      // my channel

    int i_mine = lane & 15;
    int j_mine = lane >> 4;
    float w1a = w1[i_mine * 3 + 0];
    float w1b = w1[i_mine * 3 + 1];
    float w1c = w1[i_mine * 3 + 2];
    float b1r = b1[i_mine];
    float w2h[16];
    #pragma unroll
    for (int i = 0; i < 16; i++)
        w2h[i] = w2[ch * 16 + i];
    float b2h = b2[ch];

    int base_m = m0 + qg * 8;
    for (int t = 0; t < 8; t++) {
        int m = base_m + t;                // 0..16383
        int b = m >> 12;
        int q = m & 4095;
        float fx = (float)(q & 63);
        float fy = (float)(q >> 6);

        int n0 = __ldg(&g_knn[m * 3]);
        int n1 = __ldg(&g_knn[m * 3 + 1]);
        int n2 = __ldg(&g_knn[m * 3 + 2]);
        const float* uvb = uv + (size_t)b * 2 * NPTS;

        // feature gathers for my channel half (coalesced per warp)
        float f0h = g_f3t[((size_t)(b * NPTS + n0)) * C_ + ch];
        float f1h = g_f3t[((size_t)(b * NPTS + n1)) * C_ + ch];
        float f2h = g_f3t[((size_t)(b * NPTS + n2)) * C_ + ch];

        // h for my (i_mine, j_mine) neighbor (identical in both halves)
        int   na = j_mine ? n1 : n0;
        float ua = uvb[na], va = uvb[NPTS + na];
        float oxa = ua - fx, oya = va - fy;
        float nrma = sqrtf(oxa * oxa + oya * oya);
        float ha = fmaf(w1c, nrma, fmaf(w1b, oya, w1a * oxa)) + b1r;
        ha = ha >= 0.f ? ha : LRELU_SLOPE * ha;
        float ub = uvb[n2], vb = uvb[NPTS + n2];
        float oxb = ub - fx, oyb = vb - fy;
        float nrmb = sqrtf(oxb * oxb + oyb * oyb);
        float hb = fmaf(w1c, nrmb, fmaf(w1b, oyb, w1a * oxb)) + b1r;
        hb = hb >= 0.f ? hb : LRELU_SLOPE * hb;

        float z0 = b2h, z1 = b2h, z2 = b2h;
        #pragma unroll
        for (int i = 0; i < 16; i++) {
            float h0 = __shfl_sync(0xffffffffu, ha, i);
            float h1 = __shfl_sync(0xffffffffu, ha, 16 + i);
            float h2 = __shfl_sync(0xffffffffu, hb, i);
            z0 = fmaf(w2h[i], h0, z0);
            z1 = fmaf(w2h[i], h1, z1);
            z2 = fmaf(w2h[i], h2, z2);
        }
        float s0 = 1.f / (1.f + __expf(-z0));
        float s1 = 1.f / (1.f + __expf(-z1));
        float s2 = 1.f / (1.f + __expf(-z2));

        float f = fmaf(s2, f2h, fmaf(s1, f1h, s0 * f0h));

        int r = qg * 8 + t;               // row within tile
        Fs[r * 64 + ((ch + r) & 63)] = f;
    }
    __syncthreads();

    // ---- phase 2: GEMM (64 rows x 64 out-channels), thread = 1 row x 8 outputs ----
    int row = lane + 32 * (wid & 1);
    int og  = wid >> 1;               // uniform per warp -> broadcast LDS for W
    float acc[8];
    #pragma unroll
    for (int oi = 0; oi < 8; oi++) acc[oi] = 0.f;

    #pragma unroll 8
    for (int c = 0; c < 64; c++) {
        float4 wv0 = *(const float4*)&Wt[c * 64 + og * 8];
        float4 wv1 = *(const float4*)&Wt[c * 64 + og * 8 + 4];
        float f = Fs[row * 64 + ((c + row) & 63)];
        acc[0] = fmaf(wv0.x, f, acc[0]);
        acc[1] = fmaf(wv0.y, f, acc[1]);
        acc[2] = fmaf(wv0.z, f, acc[2]);
        acc[3] = fmaf(wv0.w, f, acc[3]);
        acc[4] = fmaf(wv1.x, f, acc[4]);
        acc[5] = fmaf(wv1.y, f, acc[5]);
        acc[6] = fmaf(wv1.z, f, acc[6]);
        acc[7] = fmaf(wv1.w, f, acc[7]);
    }
    {
        int m = m0 + row;
        int b = m >> 12;
        int q = m & 4095;
        #pragma unroll
        for (int oi = 0; oi < 8; oi++) {
            int o = og * 8 + oi;
            float v = acc[oi] + __ldg(&b_out[o]);
            v = v >= 0.f ? v : LRELU_SLOPE * v;
            out[((size_t)(b * 64 + o) << 12) + q] = v;
        }
    }
}

// ---------------- launch: fork/join graph ----------------
// stream0: bin -> transpose -> [wait knn] -> fused
// s2:      [wait bin] -> knn
static cudaStream_t g_s2 = nullptr;
static cudaEvent_t  g_evBin = nullptr, g_evKnn = nullptr;

extern "C" void kernel_launch(void* const* d_in, const int* in_sizes, int n_in,
                              void* d_out, int out_size) {
    const float* uv      = (const float*)d_in[0];
    // d_in[1] = feat_2d: shape-only in reference, unused
    const float* feat_3d = (const float*)d_in[2];
    const float* w1      = (const float*)d_in[3];
    const float* b1      = (const float*)d_in[4];
    const float* w2      = (const float*)d_in[5];
    const float* b2      = (const float*)d_in[6];
    const float* w_out   = (const float*)d_in[7];
    const float* b_out   = (const float*)d_in[8];
    float* out = (float*)d_out;

    if (!g_s2) {
        cudaStreamCreateWithFlags(&g_s2, cudaStreamNonBlocking);
        cudaEventCreateWithFlags(&g_evBin, cudaEventDisableTiming);
        cudaEventCreateWithFlags(&g_evKnn, cudaEventDisableTiming);
    }

    bin_points<<<64, 256>>>(uv);
    cudaEventRecord(g_evBin, 0);
    cudaStreamWaitEvent(g_s2, g_evBin, 0);
    knn_search<<<BS * NCELL, 128, 0, g_s2>>>();
    cudaEventRecord(g_evKnn, g_s2);

    transpose_f3<<<BS * 256, 128>>>(feat_3d);

    cudaStreamWaitEvent(0, g_evKnn, 0);
    fused_score_gemm<<<M_TOT / 64, 512>>>(uv, w1, b1, w2, b2, w_out, b_out, out);
}